// round 2
// baseline (speedup 1.0000x reference)
#include <cuda_runtime.h>
#include <cuda_bf16.h>

// Problem constants
#define NHEAD 16
#define DQ    1024
#define DKEY  64
#define BATCH 4
#define SEQ   2048
#define MROWS (BATCH * SEQ)          // 8192
#define OUT_ELEMS  (8192L * 1024L)           // 8,388,608
#define ATTN_ELEMS (64L * 2048L * 2048L)     // 268,435,456

// ---------------- scratch (device statics: sanctioned workaround) ----------
__device__ float g_qh[MROWS * DQ];     // [B,H,S,64]
__device__ float g_kh[MROWS * DQ];
__device__ float g_vh[MROWS * DQ];
__device__ float g_ctx[MROWS * DQ];    // [B,S,H*64]
__device__ float g_fc[MROWS * DQ];
__device__ float g_attn_fb[ATTN_ELEMS]; // fallback if attn not part of d_out

// ---------------- generic batched GEMM-NT: C[m,n] = alpha * sum_k A[m,k]*B[n,k]
// MODE 0: C row-major [M,N].  MODE 1: projection layout [B,H,S,64].
template <int MODE>
__global__ __launch_bounds__(256)
void gemm_nt(const float* __restrict__ A, const float* __restrict__ Bm,
             float* __restrict__ C, int M, int N, int K,
             long strideA, long strideB, long strideC, float alpha)
{
    constexpr int BM = 128, BN = 128, BK = 8, TM = 8, TN = 8;
    __shared__ float As[BK][BM];
    __shared__ float Bs[BK][BN];

    const int z = blockIdx.z;
    const float* Ab = A  + (long)z * strideA;
    const float* Bb = Bm + (long)z * strideB;
    float*       Cb = C  + (long)z * strideC;

    const int bm = blockIdx.y * BM;
    const int bn = blockIdx.x * BN;
    const int tid = threadIdx.x;

    const int arow  = tid >> 1;          // 0..127
    const int acol4 = (tid & 1) * 4;     // 0 or 4
    const int tx = tid & 15;             // 0..15 -> n micro
    const int ty = tid >> 4;             // 0..15 -> m micro

    float acc[TM][TN];
#pragma unroll
    for (int i = 0; i < TM; i++)
#pragma unroll
        for (int j = 0; j < TN; j++) acc[i][j] = 0.f;

    for (int k0 = 0; k0 < K; k0 += BK) {
        float4 av = *(const float4*)(Ab + (long)(bm + arow) * K + k0 + acol4);
        float4 bv = *(const float4*)(Bb + (long)(bn + arow) * K + k0 + acol4);
        As[acol4 + 0][arow] = av.x; As[acol4 + 1][arow] = av.y;
        As[acol4 + 2][arow] = av.z; As[acol4 + 3][arow] = av.w;
        Bs[acol4 + 0][arow] = bv.x; Bs[acol4 + 1][arow] = bv.y;
        Bs[acol4 + 2][arow] = bv.z; Bs[acol4 + 3][arow] = bv.w;
        __syncthreads();
#pragma unroll
        for (int kk = 0; kk < BK; kk++) {
            float a[TM], b[TN];
#pragma unroll
            for (int i = 0; i < TM; i++) a[i] = As[kk][ty * TM + i];
#pragma unroll
            for (int j = 0; j < TN; j++) b[j] = Bs[kk][tx * TN + j];
#pragma unroll
            for (int i = 0; i < TM; i++)
#pragma unroll
                for (int j = 0; j < TN; j++) acc[i][j] += a[i] * b[j];
        }
        __syncthreads();
    }

    if (MODE == 0) {
#pragma unroll
        for (int i = 0; i < TM; i++) {
            long crow = (long)(bm + ty * TM + i);
            float4 o0, o1;
            o0.x = alpha * acc[i][0]; o0.y = alpha * acc[i][1];
            o0.z = alpha * acc[i][2]; o0.w = alpha * acc[i][3];
            o1.x = alpha * acc[i][4]; o1.y = alpha * acc[i][5];
            o1.z = alpha * acc[i][6]; o1.w = alpha * acc[i][7];
            float* cp = Cb + crow * N + bn + tx * TN;
            *(float4*)(cp)     = o0;
            *(float4*)(cp + 4) = o1;
        }
    } else {
        // projection layout: n -> (h, d); m -> (b, s); dst[(b*16+h)*2048+s][64] stride
        const int n0 = bn + tx * TN;
        const int h  = n0 >> 6;
        const int d0 = n0 & 63;
#pragma unroll
        for (int i = 0; i < TM; i++) {
            const int m = bm + ty * TM + i;
            const int b = m >> 11;
            const int s = m & 2047;
            float* cp = Cb + ((long)((b * NHEAD + h) * SEQ + s)) * 64 + d0;
            float4 o0, o1;
            o0.x = acc[i][0]; o0.y = acc[i][1]; o0.z = acc[i][2]; o0.w = acc[i][3];
            o1.x = acc[i][4]; o1.y = acc[i][5]; o1.z = acc[i][6]; o1.w = acc[i][7];
            *(float4*)(cp)     = o0;
            *(float4*)(cp + 4) = o1;
        }
    }
}

// ---------------- row softmax, in place; one block per row of 2048 ----------
__global__ __launch_bounds__(256)
void softmax_kernel(float* __restrict__ attn)
{
    const long row = blockIdx.x;
    float* p = attn + row * 2048;
    const int tid = threadIdx.x;

    float4 a = ((const float4*)p)[tid];
    float4 b = ((const float4*)p)[tid + 256];

    float m = fmaxf(fmaxf(fmaxf(a.x, a.y), fmaxf(a.z, a.w)),
                    fmaxf(fmaxf(b.x, b.y), fmaxf(b.z, b.w)));
#pragma unroll
    for (int off = 16; off > 0; off >>= 1)
        m = fmaxf(m, __shfl_xor_sync(0xffffffffu, m, off));

    __shared__ float red[8];
    const int wid = tid >> 5, lane = tid & 31;
    if (lane == 0) red[wid] = m;
    __syncthreads();
    float bm = red[0];
#pragma unroll
    for (int w = 1; w < 8; w++) bm = fmaxf(bm, red[w]);

    a.x = __expf(a.x - bm); a.y = __expf(a.y - bm);
    a.z = __expf(a.z - bm); a.w = __expf(a.w - bm);
    b.x = __expf(b.x - bm); b.y = __expf(b.y - bm);
    b.z = __expf(b.z - bm); b.w = __expf(b.w - bm);

    float s = a.x + a.y + a.z + a.w + b.x + b.y + b.z + b.w;
#pragma unroll
    for (int off = 16; off > 0; off >>= 1)
        s += __shfl_xor_sync(0xffffffffu, s, off);

    __syncthreads();               // protect red[] reuse
    if (lane == 0) red[wid] = s;
    __syncthreads();
    float bs = red[0];
#pragma unroll
    for (int w = 1; w < 8; w++) bs += red[w];
    const float inv = 1.0f / bs;

    a.x *= inv; a.y *= inv; a.z *= inv; a.w *= inv;
    b.x *= inv; b.y *= inv; b.z *= inv; b.w *= inv;
    ((float4*)p)[tid]       = a;
    ((float4*)p)[tid + 256] = b;
}

// ---------------- PV: ctx[b, q, h*64+d] = sum_k attn[z,q,k] * vh[z,k,d] -----
__global__ __launch_bounds__(256)
void pv_kernel(const float* __restrict__ attn, const float* __restrict__ vh,
               float* __restrict__ ctx)
{
    constexpr int BQ = 128, BKt = 32;
    __shared__ float As[BKt][BQ];
    __shared__ float Vs[BKt][68];

    const int z = blockIdx.y;          // b*16 + h
    const int b = z >> 4, h = z & 15;
    const float* Ab = attn + (long)z * SEQ * SEQ + (long)(blockIdx.x * BQ) * SEQ;
    const float* Vb = vh + (long)z * SEQ * 64;
    const int tid = threadIdx.x;
    const int tx = tid & 15;           // d micro: tx*4
    const int ty = tid >> 4;           // q micro: ty*8

    float acc[8][4];
#pragma unroll
    for (int i = 0; i < 8; i++)
#pragma unroll
        for (int j = 0; j < 4; j++) acc[i][j] = 0.f;

    for (int k0 = 0; k0 < SEQ; k0 += BKt) {
#pragma unroll
        for (int i = 0; i < 4; i++) {
            int idx = tid + i * 256;        // f4 index within 128x32 tile
            int r = idx >> 3, c4 = (idx & 7) * 4;
            float4 v = *(const float4*)(Ab + (long)r * SEQ + k0 + c4);
            As[c4 + 0][r] = v.x; As[c4 + 1][r] = v.y;
            As[c4 + 2][r] = v.z; As[c4 + 3][r] = v.w;
        }
#pragma unroll
        for (int i = 0; i < 2; i++) {
            int idx = tid + i * 256;        // f4 index within 32x64 tile
            int r = idx >> 4, c4 = (idx & 15) * 4;
            float4 v = *(const float4*)(Vb + (long)(k0 + r) * 64 + c4);
            *(float4*)&Vs[r][c4] = v;
        }
        __syncthreads();
#pragma unroll
        for (int kk = 0; kk < BKt; kk++) {
            float a[8], vv[4];
#pragma unroll
            for (int i = 0; i < 8; i++) a[i] = As[kk][ty * 8 + i];
#pragma unroll
            for (int j = 0; j < 4; j++) vv[j] = Vs[kk][tx * 4 + j];
#pragma unroll
            for (int i = 0; i < 8; i++)
#pragma unroll
                for (int j = 0; j < 4; j++) acc[i][j] += a[i] * vv[j];
        }
        __syncthreads();
    }

#pragma unroll
    for (int i = 0; i < 8; i++) {
        int q = blockIdx.x * BQ + ty * 8 + i;
        float* cp = ctx + ((long)(b * SEQ + q)) * DQ + h * 64 + tx * 4;
        float4 o; o.x = acc[i][0]; o.y = acc[i][1]; o.z = acc[i][2]; o.w = acc[i][3];
        *(float4*)cp = o;
    }
}

// ---------------- residual add + LayerNorm; one block per row of 1024 -------
__global__ __launch_bounds__(256)
void add_ln_kernel(const float* __restrict__ fc, const float* __restrict__ res,
                   const float* __restrict__ gamma, const float* __restrict__ beta,
                   float* __restrict__ out)
{
    const long row = blockIdx.x;
    const int tid = threadIdx.x;
    float4 f = ((const float4*)(fc  + row * DQ))[tid];
    float4 r = ((const float4*)(res + row * DQ))[tid];
    float x0 = f.x + r.x, x1 = f.y + r.y, x2 = f.z + r.z, x3 = f.w + r.w;

    float s  = x0 + x1 + x2 + x3;
    float sq = x0 * x0 + x1 * x1 + x2 * x2 + x3 * x3;
#pragma unroll
    for (int off = 16; off > 0; off >>= 1) {
        s  += __shfl_xor_sync(0xffffffffu, s,  off);
        sq += __shfl_xor_sync(0xffffffffu, sq, off);
    }
    __shared__ float rs[8], rq[8];
    const int wid = tid >> 5, lane = tid & 31;
    if (lane == 0) { rs[wid] = s; rq[wid] = sq; }
    __syncthreads();
    float S = 0.f, SQ = 0.f;
#pragma unroll
    for (int w = 0; w < 8; w++) { S += rs[w]; SQ += rq[w]; }

    const float mu  = S * (1.0f / DQ);
    const float var = SQ * (1.0f / DQ) - mu * mu;
    const float rstd = rsqrtf(var + 1e-6f);

    float4 g  = ((const float4*)gamma)[tid];
    float4 be = ((const float4*)beta)[tid];
    float4 o;
    o.x = (x0 - mu) * rstd * g.x + be.x;
    o.y = (x1 - mu) * rstd * g.y + be.y;
    o.z = (x2 - mu) * rstd * g.z + be.z;
    o.w = (x3 - mu) * rstd * g.w + be.w;
    ((float4*)(out + row * DQ))[tid] = o;
}

// ---------------- launcher --------------------------------------------------
extern "C" void kernel_launch(void* const* d_in, const int* in_sizes, int n_in,
                              void* d_out, int out_size)
{
    const float* q    = (const float*)d_in[0];
    const float* k    = (const float*)d_in[1];
    const float* v    = (const float*)d_in[2];
    const float* w_q  = (const float*)d_in[3];
    const float* w_k  = (const float*)d_in[4];
    const float* w_v  = (const float*)d_in[5];
    const float* w_fc = (const float*)d_in[6];
    const float* ga   = (const float*)d_in[7];
    const float* be   = (const float*)d_in[8];
    float* out = (float*)d_out;

    float *qh, *kh, *vh, *ctx, *fc, *attn_fb;
    cudaGetSymbolAddress((void**)&qh,      g_qh);
    cudaGetSymbolAddress((void**)&kh,      g_kh);
    cudaGetSymbolAddress((void**)&vh,      g_vh);
    cudaGetSymbolAddress((void**)&ctx,     g_ctx);
    cudaGetSymbolAddress((void**)&fc,      g_fc);
    cudaGetSymbolAddress((void**)&attn_fb, g_attn_fb);

    // locate attn region in the output (tuple order: out, attn)
    float* attn;
    bool write_out = true;
    if ((long)out_size >= OUT_ELEMS + ATTN_ELEMS) {
        attn = out + OUT_ELEMS;
    } else if ((long)out_size == ATTN_ELEMS) {
        attn = out;            // attn-only output
        write_out = false;
    } else {
        attn = attn_fb;        // out-only output; attn kept in scratch
    }

    const float scale = 0.125f; // 1/sqrt(64)

    // projections: M=8192, N=1024, K=1024 -> head-major layout
    gemm_nt<1><<<dim3(8, 64, 1), 256>>>(q, w_q, qh, MROWS, DQ, DQ, 0, 0, 0, 1.0f);
    gemm_nt<1><<<dim3(8, 64, 1), 256>>>(k, w_k, kh, MROWS, DQ, DQ, 0, 0, 0, 1.0f);
    gemm_nt<1><<<dim3(8, 64, 1), 256>>>(v, w_v, vh, MROWS, DQ, DQ, 0, 0, 0, 1.0f);

    // scores: 64 batched [2048,64] x [2048,64]^T, scaled
    gemm_nt<0><<<dim3(16, 16, 64), 256>>>(qh, kh, attn, SEQ, SEQ, 64,
                                          (long)SEQ * 64, (long)SEQ * 64,
                                          (long)SEQ * SEQ, scale);

    // softmax in place
    softmax_kernel<<<64 * SEQ, 256>>>(attn);

    // PV
    pv_kernel<<<dim3(16, 64), 256>>>(attn, vh, ctx);

    if (write_out) {
        // FC: [8192,1024] x [1024,1024]^T
        gemm_nt<0><<<dim3(8, 64, 1), 256>>>(ctx, w_fc, fc, MROWS, DQ, DQ, 0, 0, 0, 1.0f);
        // residual + LN
        add_ln_kernel<<<MROWS, 256>>>(fc, q, ga, be, out);
    }
}

// round 3
// speedup vs baseline: 2.5812x; 2.5812x over previous
#include <cuda_runtime.h>
#include <cuda_bf16.h>

// Problem constants
#define NHEAD 16
#define DQ    1024
#define DKEY  64
#define BATCH 4
#define SEQ   2048
#define MROWS (BATCH * SEQ)          // 8192
#define OUT_ELEMS  (8192L * 1024L)           // 8,388,608
#define ATTN_ELEMS (64L * 2048L * 2048L)     // 268,435,456

// ---------------- scratch ---------------------------------------------------
__device__ float g_qh[MROWS * DQ];     // [B,H,S,64]
__device__ float g_kh[MROWS * DQ];
__device__ float g_vh[MROWS * DQ];
__device__ float g_ctx[MROWS * DQ];    // [B,S,H*64]
__device__ float g_fc[MROWS * DQ];
__device__ float g_attn_fb[ATTN_ELEMS];

// ---------------- tf32 helpers ---------------------------------------------
__device__ __forceinline__ unsigned f2tf32(float x) {
    unsigned r;
    asm("cvt.rna.tf32.f32 %0, %1;" : "=r"(r) : "f"(x));
    return r;
}

__device__ __forceinline__ void mma_tf32(float c[4],
                                         unsigned a0, unsigned a1, unsigned a2, unsigned a3,
                                         unsigned b0, unsigned b1) {
    asm volatile(
        "mma.sync.aligned.m16n8k8.row.col.f32.tf32.tf32.f32 "
        "{%0,%1,%2,%3}, {%4,%5,%6,%7}, {%8,%9}, {%0,%1,%2,%3};"
        : "+f"(c[0]), "+f"(c[1]), "+f"(c[2]), "+f"(c[3])
        : "r"(a0), "r"(a1), "r"(a2), "r"(a3), "r"(b0), "r"(b1));
}

// ---------------- tensor-core GEMM-NT: C[m,n] = alpha * sum_k A[m,k]*B[n,k] -
// MODE 0: C row-major [M,N] (batched).  MODE 1: projection scatter [B,H,S,64].
template <int MODE>
__global__ __launch_bounds__(256)
void gemm_nt_tc(const float* __restrict__ A, const float* __restrict__ Bm,
                float* __restrict__ C, int M, int N, int K,
                long strideA, long strideB, long strideC, float alpha)
{
    constexpr int BM = 128, BN = 128, BK = 32;
    __shared__ unsigned As[BM][BK + 4];   // stride 36 words: conflict-free frag lds
    __shared__ unsigned Bs[BN][BK + 4];

    const int z = blockIdx.z;
    const float* Ab = A  + (long)z * strideA;
    const float* Bb = Bm + (long)z * strideB;
    float*       Cb = C  + (long)z * strideC;

    const int bm = blockIdx.y * BM;
    const int bn = blockIdx.x * BN;
    const int tid  = threadIdx.x;
    const int warp = tid >> 5, lane = tid & 31;
    const int wm = (warp >> 2) * 64;   // 0 / 64
    const int wn = (warp & 3) * 32;    // 0..96
    const int g = lane >> 2, t = lane & 3;

    float acc[4][4][4];
#pragma unroll
    for (int i = 0; i < 4; i++)
#pragma unroll
        for (int j = 0; j < 4; j++)
#pragma unroll
            for (int r = 0; r < 4; r++) acc[i][j][r] = 0.f;

    const int lr = tid >> 3;        // 0..31
    const int lc = (tid & 7) * 4;   // 0..28

    for (int k0 = 0; k0 < K; k0 += BK) {
#pragma unroll
        for (int i = 0; i < 4; i++) {
            float4 va = *(const float4*)(Ab + (long)(bm + lr + i * 32) * K + k0 + lc);
            uint4 ua;
            ua.x = f2tf32(va.x); ua.y = f2tf32(va.y);
            ua.z = f2tf32(va.z); ua.w = f2tf32(va.w);
            *(uint4*)&As[lr + i * 32][lc] = ua;
            float4 vb = *(const float4*)(Bb + (long)(bn + lr + i * 32) * K + k0 + lc);
            uint4 ub;
            ub.x = f2tf32(vb.x); ub.y = f2tf32(vb.y);
            ub.z = f2tf32(vb.z); ub.w = f2tf32(vb.w);
            *(uint4*)&Bs[lr + i * 32][lc] = ub;
        }
        __syncthreads();

#pragma unroll
        for (int kk = 0; kk < BK; kk += 8) {
            unsigned af[4][4], bf[4][2];
#pragma unroll
            for (int i = 0; i < 4; i++) {
                int r = wm + i * 16;
                af[i][0] = As[r + g][kk + t];
                af[i][1] = As[r + g + 8][kk + t];
                af[i][2] = As[r + g][kk + t + 4];
                af[i][3] = As[r + g + 8][kk + t + 4];
            }
#pragma unroll
            for (int j = 0; j < 4; j++) {
                int c = wn + j * 8;
                bf[j][0] = Bs[c + g][kk + t];
                bf[j][1] = Bs[c + g][kk + t + 4];
            }
#pragma unroll
            for (int i = 0; i < 4; i++)
#pragma unroll
                for (int j = 0; j < 4; j++)
                    mma_tf32(acc[i][j], af[i][0], af[i][1], af[i][2], af[i][3],
                             bf[j][0], bf[j][1]);
        }
        __syncthreads();
    }

    // epilogue
#pragma unroll
    for (int i = 0; i < 4; i++) {
#pragma unroll
        for (int j = 0; j < 4; j++) {
            const int mrow = bm + wm + i * 16 + g;
            const int ncol = bn + wn + j * 8 + 2 * t;
            float2 lo, hi;
            lo.x = alpha * acc[i][j][0]; lo.y = alpha * acc[i][j][1];
            hi.x = alpha * acc[i][j][2]; hi.y = alpha * acc[i][j][3];
            if (MODE == 0) {
                *(float2*)(Cb + (long)mrow * N + ncol)       = lo;
                *(float2*)(Cb + (long)(mrow + 8) * N + ncol) = hi;
            } else {
                const int h = ncol >> 6, d = ncol & 63;
                int b0 = mrow >> 11, s0 = mrow & 2047;
                *(float2*)(Cb + ((long)((b0 * NHEAD + h) * SEQ + s0)) * 64 + d) = lo;
                int m2 = mrow + 8;
                int b1 = m2 >> 11, s1 = m2 & 2047;
                *(float2*)(Cb + ((long)((b1 * NHEAD + h) * SEQ + s1)) * 64 + d) = hi;
            }
        }
    }
}

// ---------------- PV (tensor core): ctx[b,q,h*64+d] = sum_k P[q,k] V[k,d] ---
__global__ __launch_bounds__(256)
void pv_tc(const float* __restrict__ attn, const float* __restrict__ vh,
           float* __restrict__ ctx)
{
    constexpr int BM = 128, BK = 32;
    __shared__ unsigned As[BM][BK + 4];   // attn tile, stride 36
    __shared__ unsigned Vs[BK][72];       // V tile [k][d], stride 72 (conflict-free)

    const int z = blockIdx.y;          // b*16 + h
    const int b = z >> 4, h = z & 15;
    const int bm = blockIdx.x * BM;
    const float* Ab = attn + (long)z * SEQ * SEQ + (long)bm * SEQ;
    const float* Vb = vh   + (long)z * SEQ * 64;

    const int tid  = threadIdx.x;
    const int warp = tid >> 5, lane = tid & 31;
    const int wm = (warp >> 2) * 64;   // 0 / 64
    const int wn = (warp & 3) * 16;    // 0..48
    const int g = lane >> 2, t = lane & 3;

    float acc[4][2][4];
#pragma unroll
    for (int i = 0; i < 4; i++)
#pragma unroll
        for (int j = 0; j < 2; j++)
#pragma unroll
            for (int r = 0; r < 4; r++) acc[i][j][r] = 0.f;

    const int lr = tid >> 3;        // 0..31
    const int lc = (tid & 7) * 4;   // 0..28
    const int vr = tid >> 4;        // 0..15
    const int vc = (tid & 15) * 4;  // 0..60

    for (int k0 = 0; k0 < SEQ; k0 += BK) {
#pragma unroll
        for (int i = 0; i < 4; i++) {
            float4 va = *(const float4*)(Ab + (long)(lr + i * 32) * SEQ + k0 + lc);
            uint4 ua;
            ua.x = f2tf32(va.x); ua.y = f2tf32(va.y);
            ua.z = f2tf32(va.z); ua.w = f2tf32(va.w);
            *(uint4*)&As[lr + i * 32][lc] = ua;
        }
#pragma unroll
        for (int i = 0; i < 2; i++) {
            float4 vv = *(const float4*)(Vb + (long)(k0 + vr + i * 16) * 64 + vc);
            uint4 uv;
            uv.x = f2tf32(vv.x); uv.y = f2tf32(vv.y);
            uv.z = f2tf32(vv.z); uv.w = f2tf32(vv.w);
            *(uint4*)&Vs[vr + i * 16][vc] = uv;
        }
        __syncthreads();

#pragma unroll
        for (int kk = 0; kk < BK; kk += 8) {
            unsigned af[4][4], bf[2][2];
#pragma unroll
            for (int i = 0; i < 4; i++) {
                int r = wm + i * 16;
                af[i][0] = As[r + g][kk + t];
                af[i][1] = As[r + g + 8][kk + t];
                af[i][2] = As[r + g][kk + t + 4];
                af[i][3] = As[r + g + 8][kk + t + 4];
            }
#pragma unroll
            for (int j = 0; j < 2; j++) {
                int c = wn + j * 8;
                bf[j][0] = Vs[kk + t][c + g];
                bf[j][1] = Vs[kk + t + 4][c + g];
            }
#pragma unroll
            for (int i = 0; i < 4; i++)
#pragma unroll
                for (int j = 0; j < 2; j++)
                    mma_tf32(acc[i][j], af[i][0], af[i][1], af[i][2], af[i][3],
                             bf[j][0], bf[j][1]);
        }
        __syncthreads();
    }

#pragma unroll
    for (int i = 0; i < 4; i++) {
#pragma unroll
        for (int j = 0; j < 2; j++) {
            const int q = bm + wm + i * 16 + g;
            const int d = wn + j * 8 + 2 * t;
            float2 lo, hi;
            lo.x = acc[i][j][0]; lo.y = acc[i][j][1];
            hi.x = acc[i][j][2]; hi.y = acc[i][j][3];
            *(float2*)(ctx + ((long)(b * SEQ + q)) * DQ + h * 64 + d)       = lo;
            *(float2*)(ctx + ((long)(b * SEQ + q + 8)) * DQ + h * 64 + d)   = hi;
        }
    }
}

// ---------------- row softmax, in place; one block per row of 2048 ----------
__global__ __launch_bounds__(256)
void softmax_kernel(float* __restrict__ attn)
{
    const long row = blockIdx.x;
    float* p = attn + row * 2048;
    const int tid = threadIdx.x;

    float4 a = ((const float4*)p)[tid];
    float4 b = ((const float4*)p)[tid + 256];

    float m = fmaxf(fmaxf(fmaxf(a.x, a.y), fmaxf(a.z, a.w)),
                    fmaxf(fmaxf(b.x, b.y), fmaxf(b.z, b.w)));
#pragma unroll
    for (int off = 16; off > 0; off >>= 1)
        m = fmaxf(m, __shfl_xor_sync(0xffffffffu, m, off));

    __shared__ float red[8];
    const int wid = tid >> 5, lane = tid & 31;
    if (lane == 0) red[wid] = m;
    __syncthreads();
    float bm = red[0];
#pragma unroll
    for (int w = 1; w < 8; w++) bm = fmaxf(bm, red[w]);

    a.x = __expf(a.x - bm); a.y = __expf(a.y - bm);
    a.z = __expf(a.z - bm); a.w = __expf(a.w - bm);
    b.x = __expf(b.x - bm); b.y = __expf(b.y - bm);
    b.z = __expf(b.z - bm); b.w = __expf(b.w - bm);

    float s = a.x + a.y + a.z + a.w + b.x + b.y + b.z + b.w;
#pragma unroll
    for (int off = 16; off > 0; off >>= 1)
        s += __shfl_xor_sync(0xffffffffu, s, off);

    __syncthreads();
    if (lane == 0) red[wid] = s;
    __syncthreads();
    float bs = red[0];
#pragma unroll
    for (int w = 1; w < 8; w++) bs += red[w];
    const float inv = 1.0f / bs;

    a.x *= inv; a.y *= inv; a.z *= inv; a.w *= inv;
    b.x *= inv; b.y *= inv; b.z *= inv; b.w *= inv;
    ((float4*)p)[tid]       = a;
    ((float4*)p)[tid + 256] = b;
}

// ---------------- residual add + LayerNorm ----------------------------------
__global__ __launch_bounds__(256)
void add_ln_kernel(const float* __restrict__ fc, const float* __restrict__ res,
                   const float* __restrict__ gamma, const float* __restrict__ beta,
                   float* __restrict__ out)
{
    const long row = blockIdx.x;
    const int tid = threadIdx.x;
    float4 f = ((const float4*)(fc  + row * DQ))[tid];
    float4 r = ((const float4*)(res + row * DQ))[tid];
    float x0 = f.x + r.x, x1 = f.y + r.y, x2 = f.z + r.z, x3 = f.w + r.w;

    float s  = x0 + x1 + x2 + x3;
    float sq = x0 * x0 + x1 * x1 + x2 * x2 + x3 * x3;
#pragma unroll
    for (int off = 16; off > 0; off >>= 1) {
        s  += __shfl_xor_sync(0xffffffffu, s,  off);
        sq += __shfl_xor_sync(0xffffffffu, sq, off);
    }
    __shared__ float rs[8], rq[8];
    const int wid = tid >> 5, lane = tid & 31;
    if (lane == 0) { rs[wid] = s; rq[wid] = sq; }
    __syncthreads();
    float S = 0.f, SQ = 0.f;
#pragma unroll
    for (int w = 0; w < 8; w++) { S += rs[w]; SQ += rq[w]; }

    const float mu  = S * (1.0f / DQ);
    const float var = SQ * (1.0f / DQ) - mu * mu;
    const float rstd = rsqrtf(var + 1e-6f);

    float4 g  = ((const float4*)gamma)[tid];
    float4 be = ((const float4*)beta)[tid];
    float4 o;
    o.x = (x0 - mu) * rstd * g.x + be.x;
    o.y = (x1 - mu) * rstd * g.y + be.y;
    o.z = (x2 - mu) * rstd * g.z + be.z;
    o.w = (x3 - mu) * rstd * g.w + be.w;
    ((float4*)(out + row * DQ))[tid] = o;
}

// ---------------- launcher --------------------------------------------------
extern "C" void kernel_launch(void* const* d_in, const int* in_sizes, int n_in,
                              void* d_out, int out_size)
{
    const float* q    = (const float*)d_in[0];
    const float* k    = (const float*)d_in[1];
    const float* v    = (const float*)d_in[2];
    const float* w_q  = (const float*)d_in[3];
    const float* w_k  = (const float*)d_in[4];
    const float* w_v  = (const float*)d_in[5];
    const float* w_fc = (const float*)d_in[6];
    const float* ga   = (const float*)d_in[7];
    const float* be   = (const float*)d_in[8];
    float* out = (float*)d_out;

    float *qh, *kh, *vh, *ctx, *fc, *attn_fb;
    cudaGetSymbolAddress((void**)&qh,      g_qh);
    cudaGetSymbolAddress((void**)&kh,      g_kh);
    cudaGetSymbolAddress((void**)&vh,      g_vh);
    cudaGetSymbolAddress((void**)&ctx,     g_ctx);
    cudaGetSymbolAddress((void**)&fc,      g_fc);
    cudaGetSymbolAddress((void**)&attn_fb, g_attn_fb);

    float* attn;
    bool write_out = true;
    if ((long)out_size >= OUT_ELEMS + ATTN_ELEMS) {
        attn = out + OUT_ELEMS;
    } else if ((long)out_size == ATTN_ELEMS) {
        attn = out;
        write_out = false;
    } else {
        attn = attn_fb;
    }

    const float scale = 0.125f; // 1/sqrt(64)

    // projections: M=8192, N=1024, K=1024 -> head-major layout
    gemm_nt_tc<1><<<dim3(8, 64, 1), 256>>>(q, w_q, qh, MROWS, DQ, DQ, 0, 0, 0, 1.0f);
    gemm_nt_tc<1><<<dim3(8, 64, 1), 256>>>(k, w_k, kh, MROWS, DQ, DQ, 0, 0, 0, 1.0f);
    gemm_nt_tc<1><<<dim3(8, 64, 1), 256>>>(v, w_v, vh, MROWS, DQ, DQ, 0, 0, 0, 1.0f);

    // scores: 64 batched [2048,64] x [2048,64]^T, scaled
    gemm_nt_tc<0><<<dim3(16, 16, 64), 256>>>(qh, kh, attn, SEQ, SEQ, 64,
                                             (long)SEQ * 64, (long)SEQ * 64,
                                             (long)SEQ * SEQ, scale);

    // softmax in place
    softmax_kernel<<<64 * SEQ, 256>>>(attn);

    // PV
    pv_tc<<<dim3(16, 64), 256>>>(attn, vh, ctx);

    if (write_out) {
        // FC: [8192,1024] x [1024,1024]^T
        gemm_nt_tc<0><<<dim3(8, 64, 1), 256>>>(ctx, w_fc, fc, MROWS, DQ, DQ, 0, 0, 0, 1.0f);
        // residual + LN
        add_ln_kernel<<<MROWS, 256>>>(fc, q, ga, be, out);
    }
}